// round 3
// baseline (speedup 1.0000x reference)
#include <cuda_runtime.h>

// DTW loss: B independent 1024x1024 wavefront DPs, fused with path-loss
// accumulation (W[i,j] = w(i,j) + W[argmin-pred]) so no backtrack is needed.
//
// R2: barrier-free warp pipeline. Warp w owns a 128-row band; the only
// cross-warp dependency (warp w-1's last row, one diagonal behind) flows
// through a full-length shared-memory ring with release/acquire counters.
// Warps self-pace with ~128 diagonals of slack -> issue-bound, no convoy.

#define NN 1024
#define MM 1024
#define RR 4                 // rows per thread
#define TT 256               // threads per block
#define NWARP 8
#define BAND (RR * 32)       // 128 rows per warp
#define RING 2048            // full-length ring: no wraparound, no backpressure

#define FINF (__int_as_float(0x7f800000))

__device__ float g_partial[64];

static __forceinline__ __device__ float fsqrt_approx(float x) {
    float r;
    asm("sqrt.approx.f32 %0, %1;" : "=f"(r) : "f"(x));
    return r;
}

static __forceinline__ __device__ unsigned smem_u32(const void* p) {
    return (unsigned)__cvta_generic_to_shared(p);
}

// dynamic smem layout
#define RING_F2   (7 * RING)                      // warps 0..6 produce
#define STX_ELEMS 1280                            // 1023 + (1023>>2) + 1 rounded
#define SMEM_BYTES (RING_F2 * 8 + 2 * STX_ELEMS * 4 + 8 * 4)

__global__ void __launch_bounds__(TT, 1)
dtw_forward_kernel(const float* __restrict__ preds,
                   const float* __restrict__ targs,
                   const float* __restrict__ subcoef)
{
    extern __shared__ unsigned char smem_raw[];
    float2*   ring = (float2*)smem_raw;               // [7][RING]
    float*    sTx  = (float*)(ring + RING_F2);        // [STX_ELEMS] swizzled
    float*    sTy  = sTx + STX_ELEMS;
    unsigned* cnt  = (unsigned*)(sTy + STX_ELEMS);    // [8] progress counters

    const int b    = blockIdx.x;
    const int tid  = threadIdx.x;
    const int lane = tid & 31;
    const int warp = tid >> 5;

    const float* __restrict__ pb = preds + (size_t)b * NN * 4;
    const float* __restrict__ tb = targs + (size_t)b * MM * 4;

    // stage target basis coords, bank-swizzled so stride-4 lane access is
    // conflict-free (idx = j + j/4 -> stride 5 words, gcd(5,32)=1)
    for (int j = tid; j < MM; j += TT) {
        int idx = j + (j >> 2);
        sTx[idx] = tb[j * 4 + 0];
        sTy[idx] = tb[j * 4 + 1];
    }
    if (tid < NWARP) cnt[tid] = 0;

    const float s0 = subcoef[0];
    const float s1 = subcoef[1];

    const int i0 = tid * RR;           // first owned row
    float px[RR], py[RR];
#pragma unroll
    for (int r = 0; r < RR; ++r) {
        px[r] = pb[(i0 + r) * 4 + 0];
        py[r] = pb[(i0 + r) * 4 + 1];
    }

    float D1[RR], D2[RR], W1[RR], W2[RR];
#pragma unroll
    for (int r = 0; r < RR; ++r) { D1[r] = FINF; D2[r] = FINF; W1[r] = 0.f; W2[r] = 0.f; }

    // neighbor-row history cache (diag k-2 values = previous step's shuffle).
    // warp0/lane0 seeds pD=0 so cell (0,0) picks the "diag" predecessor with
    // best=0, W=0 -- replaces the per-cell isinf special case.
    float pD = (warp == 0 && lane == 0) ? 0.f : FINF;
    float pW = 0.f;

    const unsigned myCnt   = smem_u32(&cnt[warp]);
    const unsigned prevCnt = smem_u32(&cnt[warp > 0 ? warp - 1 : 0]);

    __syncthreads();   // the only full barrier: staging + counter init

    const int kstart  = warp * BAND;
    const int kend    = kstart + BAND - 1 + MM - 1;   // inclusive
    const int pollend = kstart + MM - 1;              // last step lane0 row can be valid

    // peel: lane0 consumers need ring[kstart-2] as their first diag-k-2 value
    if (lane == 0 && warp > 0) {
        unsigned c;
        do {
            asm volatile("ld.acquire.cta.shared.u32 %0, [%1];" : "=r"(c) : "r"(prevCnt));
        } while (c < (unsigned)(kstart - 1));
        float2 e = ring[(warp - 1) * RING + (kstart - 2)];
        pD = e.x; pW = e.y;
    }

    // sliding window of target coords: slot rr holds sT[j0-rr]
    float tx[RR], ty[RR];
#pragma unroll
    for (int r = 0; r < RR; ++r) { tx[r] = sTx[0]; ty[r] = sTy[0]; }

#pragma unroll 4
    for (int k = kstart; k <= kend; ++k) {
        float nD1 = __shfl_up_sync(0xffffffffu, D1[RR - 1], 1);
        float nW1 = __shfl_up_sync(0xffffffffu, W1[RR - 1], 1);
        if (lane == 0) {
            if (warp == 0) {
                nD1 = FINF; nW1 = 0.f;
            } else if (k <= pollend) {
                unsigned c;
                do {
                    asm volatile("ld.acquire.cta.shared.u32 %0, [%1];" : "=r"(c) : "r"(prevCnt));
                } while (c < (unsigned)k);
                float2 e = ring[(warp - 1) * RING + (k - 1)];
                nD1 = e.x; nW1 = e.y;
            } else {
                nD1 = FINF; nW1 = 0.f;   // producer finished; cells here invalid
            }
        }
        const float nD2 = pD, nW2 = pW;
        pD = nD1; pW = nW1;

        const int j0 = k - i0;
        int jl = j0 < 0 ? 0 : (j0 > MM - 1 ? MM - 1 : j0);
        int ji = jl + (jl >> 2);
        tx[3] = tx[2]; ty[3] = ty[2];
        tx[2] = tx[1]; ty[2] = ty[1];
        tx[1] = tx[0]; ty[1] = ty[0];
        tx[0] = sTx[ji]; ty[0] = sTy[ji];

#pragma unroll
        for (int rr = RR - 1; rr >= 0; --rr) {
            float up, dg, wu, wd;
            if (rr == 0) { up = nD1; dg = nD2; wu = nW1; wd = nW2; }
            else         { up = D1[rr - 1]; dg = D2[rr - 1]; wu = W1[rr - 1]; wd = W2[rr - 1]; }
            const float lf = D1[rr];
            const float wl = W1[rr];

            const float dx = px[rr] - tx[rr];
            const float dy = py[rr] - ty[rr];
            const float c  = fsqrt_approx(dx * dx + dy * dy);
            const float w  = fabsf(dx) * s0 + fabsf(dy) * s1;

            const float best = fminf(fminf(dg, up), lf);
            // first-min-wins over [diag, up, left] (matches jnp.argmin)
            float ws = (up <= lf) ? wu : wl;
            ws = ((dg <= up) && (dg <= lf)) ? wd : ws;

            const bool valid = (unsigned)(j0 - rr) < (unsigned)MM;
            const float nD = valid ? (c + best) : FINF;
            const float nW = valid ? (w + ws)   : 0.f;
            D2[rr] = D1[rr]; D1[rr] = nD;
            W2[rr] = W1[rr]; W1[rr] = nW;
        }

        if (warp < NWARP - 1 && lane == 31) {
            ring[warp * RING + k] = make_float2(D1[RR - 1], W1[RR - 1]);
            asm volatile("st.release.cta.shared.u32 [%0], %1;"
                         :: "r"(myCnt), "r"((unsigned)(k + 1)) : "memory");
        }
    }

    if (tid == TT - 1)                 // row N-1: W1[RR-1] == W[N-1][M-1]
        g_partial[b] = W1[RR - 1];
}

__global__ void dtw_reduce_kernel(float* __restrict__ out, int B)
{
    float s = 0.f;
    for (int i = 0; i < B; ++i) s += g_partial[i];
    out[0] = s;
}

extern "C" void kernel_launch(void* const* d_in, const int* in_sizes, int n_in,
                              void* d_out, int out_size)
{
    const float* preds   = (const float*)d_in[0];
    const float* targs   = (const float*)d_in[1];
    const float* subcoef = (const float*)d_in[2];
    float* out = (float*)d_out;

    int B = in_sizes[0] / (NN * 4);
    if (B < 1) B = 1;
    if (B > 64) B = 64;

    cudaFuncSetAttribute(dtw_forward_kernel,
                         cudaFuncAttributeMaxDynamicSharedMemorySize, SMEM_BYTES);

    dtw_forward_kernel<<<B, TT, SMEM_BYTES>>>(preds, targs, subcoef);
    dtw_reduce_kernel<<<1, 1>>>(out, B);
}

// round 4
// speedup vs baseline: 3.5156x; 3.5156x over previous
#include <cuda_runtime.h>

// DTW loss: 32 independent 1024x1024 wavefront DPs, fused with path-loss
// accumulation (W[i,j] = w(i,j) + W[argmin-pred]) -> no backtrack needed.
//
// R3: warp pipeline (warp w owns a 128-row band) with CHUNKED handoff:
// producer releases its progress counter once per SCH=32 diagonals and the
// consumer acquire-polls once per chunk (with __nanosleep backoff, fixing the
// hi-wid-first spin priority inversion seen in R2), then reads the boundary
// ring with plain LDS. Sentinel-padded targets remove all per-cell
// validity predicates/clamps.

#define NN 1024
#define MM 1024
#define RR 4                 // rows per thread
#define TT 256               // threads per block
#define NWARP 8
#define BAND 128             // rows per warp
#define RING 2048
#define SCH 32               // diagonals per sync chunk (128 % SCH == 0)

#define FINF (__int_as_float(0x7f800000))
#define SENT 1.0e18f

__device__ float g_partial[64];

static __forceinline__ __device__ float fsqrt_approx(float x) {
    float r;
    asm("sqrt.approx.f32 %0, %1;" : "=f"(r) : "f"(x));
    return r;
}
static __forceinline__ __device__ unsigned smem_u32(const void* p) {
    return (unsigned)__cvta_generic_to_shared(p);
}

// target array: logical j in [-PADF, MM-1+PADF], swizzled idx = u + u/4
#define PADF 127
#define STN  1600
#define RING_F2 (7 * RING)
#define SMEM_BYTES (RING_F2 * 8 + 2 * STN * 4 + 8 * 4)

__global__ void __launch_bounds__(TT, 1)
dtw_forward_kernel(const float* __restrict__ preds,
                   const float* __restrict__ targs,
                   const float* __restrict__ subcoef)
{
    extern __shared__ unsigned char smem_raw[];
    float2*   ring = (float2*)smem_raw;               // [7][RING]
    float*    sTx  = (float*)(ring + RING_F2);        // [STN] swizzled + padded
    float*    sTy  = sTx + STN;
    unsigned* cnt  = (unsigned*)(sTy + STN);          // [8] progress counters

    const int b    = blockIdx.x;
    const int tid  = threadIdx.x;
    const int lane = tid & 31;
    const int warp = tid >> 5;

    const float* __restrict__ pb = preds + (size_t)b * NN * 4;
    const float* __restrict__ tb = targs + (size_t)b * MM * 4;

    // stage targets with front/back sentinel pad; swizzle idx = u + u/4
    // (stride-5 words -> conflict-free for the stride-4 lane access pattern)
    for (int u = tid; u < PADF + MM + PADF + 1; u += TT) {
        int j = u - PADF;
        int idx = u + (u >> 2);
        bool in = (unsigned)j < (unsigned)MM;
        int jc = in ? j : 0;
        sTx[idx] = in ? tb[jc * 4 + 0] : SENT;
        sTy[idx] = in ? tb[jc * 4 + 1] : SENT;
    }
    if (tid < NWARP) cnt[tid] = 0;

    const float s0 = subcoef[0];
    const float s1 = subcoef[1];

    const int i0 = tid * RR;
    float px[RR], py[RR];
#pragma unroll
    for (int r = 0; r < RR; ++r) {
        px[r] = pb[(i0 + r) * 4 + 0];
        py[r] = pb[(i0 + r) * 4 + 1];
    }

    float D1[RR], D2[RR], W1[RR], W2[RR];
#pragma unroll
    for (int r = 0; r < RR; ++r) { D1[r] = FINF; D2[r] = FINF; W1[r] = 0.f; W2[r] = 0.f; }

    // diag-(k-2) neighbor-row cache; warp0/lane0 seeds 0 for cell (0,0)
    float pD = (warp == 0 && lane == 0) ? 0.f : FINF;
    float pW = 0.f;

    const unsigned myCnt   = smem_u32(&cnt[warp]);
    const unsigned prevCnt = smem_u32(&cnt[warp > 0 ? warp - 1 : 0]);

    __syncthreads();

    const int kstart  = warp * BAND;
    const int kend    = kstart + BAND - 1 + MM - 1;
    const int pollend = kstart + MM - 1;

    // chunk-0 poll (whole warp, uniform) + peel of ring[kstart-2] for pD
    if (warp > 0) {
        int need = kstart + SCH - 1;
        if (need > pollend) need = pollend;
        unsigned c;
        asm volatile("ld.acquire.cta.shared.u32 %0, [%1];" : "=r"(c) : "r"(prevCnt));
        while ((int)c < need) {
            __nanosleep(64);
            asm volatile("ld.acquire.cta.shared.u32 %0, [%1];" : "=r"(c) : "r"(prevCnt));
        }
        if (lane == 0) {
            float2 e = ring[(warp - 1) * RING + (kstart - 2)];
            pD = e.x; pW = e.y;
        }
    }

    // sliding target window: after the in-loop shift, tx[rr] = sT[j0 - rr]
    const int j0f = kstart - i0;
    float tx[RR], ty[RR];
#pragma unroll
    for (int q = 0; q < RR - 1; ++q) {
        int u = j0f - 1 - q + PADF;
        int ii = u + (u >> 2);
        tx[q] = sTx[ii]; ty[q] = sTy[ii];
    }
    tx[RR - 1] = SENT; ty[RR - 1] = SENT;

#pragma unroll 4
    for (int k = kstart; k <= kend; ++k) {
        const int rel = k - kstart;

        // per-chunk acquire poll (uniform across warp, nanosleep backoff)
        if (warp > 0 && rel != 0 && (rel & (SCH - 1)) == 0 && k <= pollend) {
            int need = k + SCH - 1;
            if (need > pollend) need = pollend;
            unsigned c;
            asm volatile("ld.acquire.cta.shared.u32 %0, [%1];" : "=r"(c) : "r"(prevCnt));
            while ((int)c < need) {
                __nanosleep(64);
                asm volatile("ld.acquire.cta.shared.u32 %0, [%1];" : "=r"(c) : "r"(prevCnt));
            }
        }

        float nD1 = __shfl_up_sync(0xffffffffu, D1[RR - 1], 1);
        float nW1 = __shfl_up_sync(0xffffffffu, W1[RR - 1], 1);
        if (lane == 0) {
            if (warp == 0 || k > pollend) {
                nD1 = FINF; nW1 = 0.f;
            } else {
                float2 e = ring[(warp - 1) * RING + (k - 1)];
                nD1 = e.x; nW1 = e.y;
            }
        }
        const float nD2 = pD, nW2 = pW;
        pD = nD1; pW = nW1;

        // slide target window, load sT[j0] (sentinel-padded, no clamp)
        const int j0 = k - i0;
        int u = j0 + PADF;
        int ii = u + (u >> 2);
        tx[3] = tx[2]; ty[3] = ty[2];
        tx[2] = tx[1]; ty[2] = ty[1];
        tx[1] = tx[0]; ty[1] = ty[0];
        tx[0] = sTx[ii]; ty[0] = sTy[ii];

#pragma unroll
        for (int rr = RR - 1; rr >= 0; --rr) {
            float up, dg, wu, wd;
            if (rr == 0) { up = nD1; dg = nD2; wu = nW1; wd = nW2; }
            else         { up = D1[rr - 1]; dg = D2[rr - 1]; wu = W1[rr - 1]; wd = W2[rr - 1]; }
            const float lf = D1[rr];
            const float wl = W1[rr];

            const float dx = px[rr] - tx[rr];
            const float dy = py[rr] - ty[rr];
            const float c  = fsqrt_approx(dx * dx + dy * dy);
            const float w  = fabsf(dx) * s0 + fabsf(dy) * s1;

            const float best = fminf(fminf(dg, up), lf);
            // first-min-wins over [diag, up, left] (matches jnp.argmin)
            float ws = (up <= lf) ? wu : wl;
            ws = ((dg <= up) && (dg <= lf)) ? wd : ws;

            D2[rr] = D1[rr]; D1[rr] = c + best;
            W2[rr] = W1[rr]; W1[rr] = w + ws;
        }

        // boundary publish; counter release once per chunk (+ at the end)
        if (warp < NWARP - 1 && lane == 31) {
            ring[warp * RING + k] = make_float2(D1[RR - 1], W1[RR - 1]);
            if ((rel & (SCH - 1)) == (SCH - 1) || k == kend) {
                asm volatile("st.release.cta.shared.u32 [%0], %1;"
                             :: "r"(myCnt), "r"((unsigned)(k + 1)) : "memory");
            }
        }
    }

    if (tid == TT - 1)                 // row N-1: W1[RR-1] == W[N-1][M-1]
        g_partial[b] = W1[RR - 1];
}

__global__ void dtw_reduce_kernel(float* __restrict__ out, int B)
{
    int l = threadIdx.x;
    float s = 0.f;
    if (l < B)      s += g_partial[l];
    if (l + 32 < B) s += g_partial[l + 32];
#pragma unroll
    for (int o = 16; o; o >>= 1) s += __shfl_xor_sync(0xffffffffu, s, o);
    if (l == 0) out[0] = s;
}

extern "C" void kernel_launch(void* const* d_in, const int* in_sizes, int n_in,
                              void* d_out, int out_size)
{
    const float* preds   = (const float*)d_in[0];
    const float* targs   = (const float*)d_in[1];
    const float* subcoef = (const float*)d_in[2];
    float* out = (float*)d_out;

    int B = in_sizes[0] / (NN * 4);
    if (B < 1) B = 1;
    if (B > 64) B = 64;

    cudaFuncSetAttribute(dtw_forward_kernel,
                         cudaFuncAttributeMaxDynamicSharedMemorySize, SMEM_BYTES);

    dtw_forward_kernel<<<B, TT, SMEM_BYTES>>>(preds, targs, subcoef);
    dtw_reduce_kernel<<<1, 32>>>(out, B);
}